// round 1
// baseline (speedup 1.0000x reference)
#include <cuda_runtime.h>
#include <math.h>

#define BN_ 4096
#define DN_ 512
#define KTOP 1024

// ---------------- scratch (device globals; allocation-free kernel_launch) ----
__device__ float g_fn[BN_ * DN_];            // normalized feat        (8 MB)
__device__ float g_fo[BN_ * DN_];            // normalized feat_old    (8 MB)
__device__ float g_S[2][(size_t)BN_ * BN_];  // 0: fn@fo^T  1: fn@fn^T (134 MB)
__device__ float g_pos[BN_];
__device__ float g_rowloss[BN_];
__device__ int   g_tgt[BN_];

// ---------------- targets: detect int64 vs int32, extract to int32 ----------
__global__ void extract_targets_k(const int* __restrict__ raw) {
    __shared__ int s_any;
    if (threadIdx.x == 0) s_any = 0;
    __syncthreads();
    int local = 0;
    for (int j = threadIdx.x; j < BN_; j += blockDim.x)
        if ((j & 1) && raw[j] != 0) local = 1;
    if (local) atomicOr(&s_any, 1);
    __syncthreads();
    // int64 little-endian: odd 32-bit words (high halves) are all zero.
    int is64 = (s_any == 0);
    for (int j = threadIdx.x; j < BN_; j += blockDim.x)
        g_tgt[j] = is64 ? raw[2 * j] : raw[j];
}

// ---------------- L2 normalize rows ------------------------------------------
__global__ void normalize_k(const float* __restrict__ in, int which) {
    int row = blockIdx.x;
    const float* x = in + (size_t)row * DN_;
    float* out = (which ? g_fo : g_fn) + (size_t)row * DN_;

    float s = 0.f;
    for (int j = threadIdx.x; j < DN_; j += blockDim.x) { float v = x[j]; s += v * v; }
    #pragma unroll
    for (int o = 16; o; o >>= 1) s += __shfl_xor_sync(0xffffffffu, s, o);
    __shared__ float red[4];
    int w = threadIdx.x >> 5, l = threadIdx.x & 31;
    if (l == 0) red[w] = s;
    __syncthreads();
    if (w == 0) {
        float t = (l < 4) ? red[l] : 0.f;
        #pragma unroll
        for (int o = 2; o; o >>= 1) t += __shfl_xor_sync(0xffffffffu, t, o);
        if (l == 0) red[0] = t;
    }
    __syncthreads();
    float inv = 1.f / fmaxf(sqrtf(red[0]), 1e-12f);
    for (int j = threadIdx.x; j < DN_; j += blockDim.x) out[j] = x[j] * inv;
}

// ---------------- positive logit: diag of fn@fo^T ----------------------------
__global__ void pos_k() {
    int row = blockIdx.x;
    const float* a = g_fn + (size_t)row * DN_;
    const float* b = g_fo + (size_t)row * DN_;
    float s = 0.f;
    for (int j = threadIdx.x; j < DN_; j += blockDim.x) s += a[j] * b[j];
    #pragma unroll
    for (int o = 16; o; o >>= 1) s += __shfl_xor_sync(0xffffffffu, s, o);
    __shared__ float red[4];
    int w = threadIdx.x >> 5, l = threadIdx.x & 31;
    if (l == 0) red[w] = s;
    __syncthreads();
    if (w == 0) {
        float t = (l < 4) ? red[l] : 0.f;
        #pragma unroll
        for (int o = 2; o; o >>= 1) t += __shfl_xor_sync(0xffffffffu, t, o);
        if (l == 0) g_pos[row] = t;
    }
}

// ---------------- fp32 SIMT GEMM (NT): S[z] = fn @ (z? fn : fo)^T, masked ----
#define BM 64
#define BNB 64
#define BK 32

__global__ void __launch_bounds__(256) gemm_k() {
    int mat = blockIdx.z;
    const float* Bp = mat ? g_fn : g_fo;
    float* C = g_S[mat];

    __shared__ float As[BK][68];
    __shared__ float Bs[BK][68];

    int tid = threadIdx.x;
    int row0 = blockIdx.y * BM;
    int col0 = blockIdx.x * BNB;
    int m0 = (tid >> 4) << 2;   // 0..60
    int n0 = (tid & 15) << 2;   // 0..60

    float acc[4][4] = {};

    for (int k0 = 0; k0 < DN_; k0 += BK) {
        #pragma unroll
        for (int l = 0; l < 2; l++) {
            int idx = tid + l * 256;         // 0..511
            int r = idx >> 3;                // 0..63
            int c4 = (idx & 7) << 2;         // 0,4,...,28
            float4 a = *(const float4*)(g_fn + (size_t)(row0 + r) * DN_ + k0 + c4);
            As[c4 + 0][r] = a.x; As[c4 + 1][r] = a.y; As[c4 + 2][r] = a.z; As[c4 + 3][r] = a.w;
            float4 b = *(const float4*)(Bp + (size_t)(col0 + r) * DN_ + k0 + c4);
            Bs[c4 + 0][r] = b.x; Bs[c4 + 1][r] = b.y; Bs[c4 + 2][r] = b.z; Bs[c4 + 3][r] = b.w;
        }
        __syncthreads();
        #pragma unroll 8
        for (int k = 0; k < BK; k++) {
            float4 ra = *(const float4*)(&As[k][m0]);
            float4 rb = *(const float4*)(&Bs[k][n0]);
            float av[4] = {ra.x, ra.y, ra.z, ra.w};
            float bv[4] = {rb.x, rb.y, rb.z, rb.w};
            #pragma unroll
            for (int i = 0; i < 4; i++)
                #pragma unroll
                for (int j = 0; j < 4; j++)
                    acc[i][j] = fmaf(av[i], bv[j], acc[i][j]);
        }
        __syncthreads();
    }

    const float NEGINF = __int_as_float(0xff800000);
    int ti[4], tj[4];
    #pragma unroll
    for (int i = 0; i < 4; i++) ti[i] = g_tgt[row0 + m0 + i];
    #pragma unroll
    for (int j = 0; j < 4; j++) tj[j] = g_tgt[col0 + n0 + j];

    #pragma unroll
    for (int i = 0; i < 4; i++) {
        float4 o;
        o.x = (ti[i] == tj[0]) ? NEGINF : acc[i][0];
        o.y = (ti[i] == tj[1]) ? NEGINF : acc[i][1];
        o.z = (ti[i] == tj[2]) ? NEGINF : acc[i][2];
        o.w = (ti[i] == tj[3]) ? NEGINF : acc[i][3];
        *(float4*)(C + (size_t)(row0 + m0 + i) * BN_ + col0 + n0) = o;
    }
}

// ---------------- per-row exact top-k radix select + logsumexp ---------------
__device__ __forceinline__ unsigned f2key(float v) {
    unsigned b = __float_as_uint(v);
    return (b & 0x80000000u) ? ~b : (b | 0x80000000u);
}
__device__ __forceinline__ float key2f(unsigned k) {
    unsigned b = (k & 0x80000000u) ? (k ^ 0x80000000u) : ~k;
    return __uint_as_float(b);
}

__global__ void __launch_bounds__(256) rowloss_k() {
    int row = blockIdx.x;
    __shared__ unsigned sk[2][BN_];
    __shared__ unsigned hist[256];
    __shared__ float redf[8];
    __shared__ unsigned s_T;
    __shared__ int s_krem;
    __shared__ unsigned s_maxkey;
    __shared__ float s_sum[2];

    int tid = threadIdx.x;
    if (tid == 0) s_maxkey = 0;
    __syncthreads();

    unsigned lmax = 0;
    #pragma unroll
    for (int mat = 0; mat < 2; mat++) {
        const float* R = g_S[mat] + (size_t)row * BN_;
        for (int j = tid; j < BN_; j += 256) {
            unsigned k = f2key(R[j]);
            sk[mat][j] = k;
            lmax = max(lmax, k);
        }
    }
    atomicMax(&s_maxkey, lmax);
    __syncthreads();

    float pos = g_pos[row];
    float m = fmaxf(pos, key2f(s_maxkey));   // global shift for numerical safety

    for (int mat = 0; mat < 2; mat++) {
        unsigned prefix = 0, maskv = 0;
        int krem = KTOP;
        #pragma unroll
        for (int pass = 0; pass < 4; pass++) {
            int shift = 24 - 8 * pass;
            hist[tid] = 0;
            __syncthreads();
            for (int j = tid; j < BN_; j += 256) {
                unsigned k = sk[mat][j];
                if ((k & maskv) == prefix) atomicAdd(&hist[(k >> shift) & 255u], 1u);
            }
            __syncthreads();
            if (tid == 0) {
                int cum = 0, d = 255;
                for (; d >= 0; d--) { cum += (int)hist[d]; if (cum >= krem) break; }
                s_T = prefix | ((unsigned)d << shift);
                s_krem = krem - (cum - (int)hist[d]);
            }
            __syncthreads();
            prefix = s_T;
            maskv |= (0xFFu << shift);
            krem = s_krem;
        }
        unsigned T = prefix;       // exact key of the k-th largest
        int ties = krem;           // how many elements == T belong to top-k

        float local = 0.f;
        for (int j = tid; j < BN_; j += 256) {
            unsigned k = sk[mat][j];
            if (k > T) local += __expf(100.f * (key2f(k) - m));
        }
        #pragma unroll
        for (int o = 16; o; o >>= 1) local += __shfl_xor_sync(0xffffffffu, local, o);
        if ((tid & 31) == 0) redf[tid >> 5] = local;
        __syncthreads();
        if (tid < 8) {
            float t = redf[tid];
            #pragma unroll
            for (int o = 4; o; o >>= 1) t += __shfl_xor_sync(0xffu, t, o);
            if (tid == 0)
                s_sum[mat] = t + (float)ties * __expf(100.f * (key2f(T) - m));
        }
        __syncthreads();
    }

    if (tid == 0) {
        float tot = __expf(100.f * (pos - m)) + s_sum[0] + s_sum[1];
        g_rowloss[row] = 100.f * m + logf(tot) - 100.f * pos;
    }
}

// ---------------- final mean reduction ---------------------------------------
__global__ void finalize_k(float* __restrict__ out) {
    float s = 0.f;
    for (int j = threadIdx.x; j < BN_; j += 1024) s += g_rowloss[j];
    #pragma unroll
    for (int o = 16; o; o >>= 1) s += __shfl_xor_sync(0xffffffffu, s, o);
    __shared__ float red[32];
    int w = threadIdx.x >> 5, l = threadIdx.x & 31;
    if (l == 0) red[w] = s;
    __syncthreads();
    if (w == 0) {
        float t = red[l];
        #pragma unroll
        for (int o = 16; o; o >>= 1) t += __shfl_xor_sync(0xffffffffu, t, o);
        if (l == 0) out[0] = t * (1.0f / (float)BN_);
    }
}

// ---------------- launch ------------------------------------------------------
extern "C" void kernel_launch(void* const* d_in, const int* in_sizes, int n_in,
                              void* d_out, int out_size) {
    const float* feat     = (const float*)d_in[0];
    const float* feat_old = (const float*)d_in[1];
    const int*   tgt_raw  = (const int*)d_in[2];
    float* out = (float*)d_out;

    extract_targets_k<<<1, 1024>>>(tgt_raw);
    normalize_k<<<BN_, 128>>>(feat, 0);
    normalize_k<<<BN_, 128>>>(feat_old, 1);
    pos_k<<<BN_, 128>>>();
    dim3 grid(BN_ / BNB, BN_ / BM, 2);
    gemm_k<<<grid, 256>>>();
    rowloss_k<<<BN_, 256>>>();
    finalize_k<<<1, 1024>>>(out);
}

// round 3
// speedup vs baseline: 2.2041x; 2.2041x over previous
#include <cuda_runtime.h>
#include <cuda_bf16.h>
#include <math.h>
#include <stdint.h>

#define BN_ 4096
#define DN_ 512
#define KTOP 1024
#define KEFF 1536                 // 3 bf16-split terms x 512

// ---------------- scratch (device globals; allocation-free kernel_launch) ----
__device__ float g_fn[BN_ * DN_];            // normalized feat        (8 MB)
__device__ float g_fo[BN_ * DN_];            // normalized feat_old    (8 MB)
__device__ float g_S[2][(size_t)BN_ * BN_];  // 0: fn@fo^T  1: fn@fn^T (134 MB)
__device__ __nv_bfloat16 g_An[(size_t)BN_ * KEFF];  // [fnh|fnh|fnl]  (12 MB)
__device__ __nv_bfloat16 g_Bn[(size_t)BN_ * KEFF];  // [fnh|fnl|fnh]  (12 MB)
__device__ __nv_bfloat16 g_Bo[(size_t)BN_ * KEFF];  // [foh|fol|foh]  (12 MB)
__device__ float g_pos[BN_];
__device__ float g_rowloss[BN_];
__device__ int   g_tgt[BN_];

// ================= small PTX helpers (sm_100-safe: no tcgen05) ==============
__device__ __forceinline__ uint32_t smem_u32(const void* p) {
    uint32_t a;
    asm("{ .reg .u64 t; cvta.to.shared.u64 t, %1; cvt.u32.u64 %0, t; }"
        : "=r"(a) : "l"(p));
    return a;
}
__device__ __forceinline__ void cp16(uint32_t dst, const void* src) {
    asm volatile("cp.async.cg.shared.global [%0], [%1], 16;" :: "r"(dst), "l"(src));
}
#define CP_COMMIT() asm volatile("cp.async.commit_group;" ::: "memory")
#define CP_WAIT(n)  asm volatile("cp.async.wait_group %0;" :: "n"(n) : "memory")

__device__ __forceinline__ void ldsm_x4(uint32_t* r, uint32_t addr) {
    asm volatile("ldmatrix.sync.aligned.m8n8.x4.shared.b16 {%0,%1,%2,%3}, [%4];"
                 : "=r"(r[0]), "=r"(r[1]), "=r"(r[2]), "=r"(r[3]) : "r"(addr));
}
__device__ __forceinline__ void mma16816(float* c, const uint32_t* a, const uint32_t* b) {
    asm volatile(
        "mma.sync.aligned.m16n8k16.row.col.f32.bf16.bf16.f32 "
        "{%0,%1,%2,%3}, {%4,%5,%6,%7}, {%8,%9}, {%0,%1,%2,%3};"
        : "+f"(c[0]), "+f"(c[1]), "+f"(c[2]), "+f"(c[3])
        : "r"(a[0]), "r"(a[1]), "r"(a[2]), "r"(a[3]), "r"(b[0]), "r"(b[1]));
}

// ---------------- targets: detect int64 vs int32, extract to int32 ----------
__global__ void extract_targets_k(const int* __restrict__ raw) {
    __shared__ int s_any;
    if (threadIdx.x == 0) s_any = 0;
    __syncthreads();
    int local = 0;
    for (int j = threadIdx.x; j < BN_; j += blockDim.x)
        if ((j & 1) && raw[j] != 0) local = 1;
    if (local) atomicOr(&s_any, 1);
    __syncthreads();
    int is64 = (s_any == 0);
    for (int j = threadIdx.x; j < BN_; j += blockDim.x)
        g_tgt[j] = is64 ? raw[2 * j] : raw[j];
}

// ---------------- L2 normalize rows + bf16 hi/lo split ----------------------
__global__ void normalize_k(const float* __restrict__ in, int which) {
    int row = blockIdx.x;
    const float* x = in + (size_t)row * DN_;
    float* outf = (which ? g_fo : g_fn) + (size_t)row * DN_;

    float s = 0.f;
    for (int j = threadIdx.x; j < DN_; j += blockDim.x) { float v = x[j]; s += v * v; }
    #pragma unroll
    for (int o = 16; o; o >>= 1) s += __shfl_xor_sync(0xffffffffu, s, o);
    __shared__ float red[4];
    int w = threadIdx.x >> 5, l = threadIdx.x & 31;
    if (l == 0) red[w] = s;
    __syncthreads();
    if (w == 0) {
        float t = (l < 4) ? red[l] : 0.f;
        #pragma unroll
        for (int o = 2; o; o >>= 1) t += __shfl_xor_sync(0xffffffffu, t, o);
        if (l == 0) red[0] = t;
    }
    __syncthreads();
    float inv = 1.f / fmaxf(sqrtf(red[0]), 1e-12f);

    __nv_bfloat16* A = g_An + (size_t)row * KEFF;
    __nv_bfloat16* B = (which ? g_Bo : g_Bn) + (size_t)row * KEFF;
    for (int j = threadIdx.x; j < DN_; j += blockDim.x) {
        float v = x[j] * inv;
        outf[j] = v;
        __nv_bfloat16 h = __float2bfloat16_rn(v);
        __nv_bfloat16 lo = __float2bfloat16_rn(v - __bfloat162float(h));
        if (which == 0) {                     // fn -> A=[h|h|l], Bn=[h|l|h]
            A[j] = h; A[j + DN_] = h; A[j + 2 * DN_] = lo;
            B[j] = h; B[j + DN_] = lo; B[j + 2 * DN_] = h;
        } else {                              // fo -> Bo=[h|l|h]
            B[j] = h; B[j + DN_] = lo; B[j + 2 * DN_] = h;
        }
    }
}

// ---------------- positive logit: diag of fn@fo^T ----------------------------
__global__ void pos_k() {
    int row = blockIdx.x;
    const float* a = g_fn + (size_t)row * DN_;
    const float* b = g_fo + (size_t)row * DN_;
    float s = 0.f;
    for (int j = threadIdx.x; j < DN_; j += blockDim.x) s += a[j] * b[j];
    #pragma unroll
    for (int o = 16; o; o >>= 1) s += __shfl_xor_sync(0xffffffffu, s, o);
    __shared__ float red[4];
    int w = threadIdx.x >> 5, l = threadIdx.x & 31;
    if (l == 0) red[w] = s;
    __syncthreads();
    if (w == 0) {
        float t = (l < 4) ? red[l] : 0.f;
        #pragma unroll
        for (int o = 2; o; o >>= 1) t += __shfl_xor_sync(0xffffffffu, t, o);
        if (l == 0) g_pos[row] = t;
    }
}

// ================= mma.sync bf16 GEMM: S = A(4096x1536) x B^T ================
// CTA tile 128x128, warp grid 2x4 (warp tile 64x32), KC=32, 4-slot cp.async.
#define KC 32
#define NITER (KEFF / KC)          // 48
#define ROWB 80                    // 64B data + 16B pad (conflict-free ldmatrix)
#define ATILE (128 * ROWB)         // 10240
#define STAGEB (2 * ATILE)         // 20480
#define GEMM_SMEM (4 * STAGEB)     // 81920

__global__ void __launch_bounds__(256) gemm_mma_k() {
    extern __shared__ char sm[];
    uint32_t sbase = smem_u32(sm);

    int tid = threadIdx.x, wid = tid >> 5, lane = tid & 31;
    int warpM = wid >> 2, warpN = wid & 3;
    int mat = blockIdx.z;
    const __nv_bfloat16* Ag = g_An;
    const __nv_bfloat16* Bg = mat ? g_Bn : g_Bo;
    float* C = g_S[mat];
    int row0 = blockIdx.y * 128, col0 = blockIdx.x * 128;

    // cp.async segment assignment: 1024 x 16B segs per stage (512 A, 512 B)
    int sA0 = tid, sA1 = tid + 256, sB0 = tid, sB1 = tid + 256;
    int rA0 = sA0 >> 2, gA0 = sA0 & 3, rA1 = sA1 >> 2, gA1 = sA1 & 3;
    int rB0 = sB0 >> 2, gB0 = sB0 & 3, rB1 = sB1 >> 2, gB1 = sB1 & 3;
    const char* pA0 = (const char*)(Ag + (size_t)(row0 + rA0) * KEFF) + gA0 * 16;
    const char* pA1 = (const char*)(Ag + (size_t)(row0 + rA1) * KEFF) + gA1 * 16;
    const char* pB0 = (const char*)(Bg + (size_t)(col0 + rB0) * KEFF) + gB0 * 16;
    const char* pB1 = (const char*)(Bg + (size_t)(col0 + rB1) * KEFF) + gB1 * 16;
    uint32_t dA0 = rA0 * ROWB + gA0 * 16, dA1 = rA1 * ROWB + gA1 * 16;
    uint32_t dB0 = ATILE + rB0 * ROWB + gB0 * 16, dB1 = ATILE + rB1 * ROWB + gB1 * 16;

    #define ISSUE(it) do {                                                     \
        uint32_t st = sbase + ((it) & 3) * STAGEB;                             \
        int ko = (it) * 64;                                                    \
        cp16(st + dA0, pA0 + ko); cp16(st + dA1, pA1 + ko);                    \
        cp16(st + dB0, pB0 + ko); cp16(st + dB1, pB1 + ko);                    \
    } while (0)

    ISSUE(0); CP_COMMIT();
    ISSUE(1); CP_COMMIT();
    ISSUE(2); CP_COMMIT();

    float acc[4][4][4] = {};
    // ldmatrix per-thread address offsets (within stage)
    uint32_t aoff = (uint32_t)((warpM * 64 + (lane & 15)) * ROWB + (lane >> 4) * 16);
    uint32_t boff = (uint32_t)(ATILE +
        (warpN * 32 + (lane & 7) + (lane >> 4) * 8) * ROWB + ((lane >> 3) & 1) * 16);

    for (int it = 0; it < NITER; it++) {
        CP_WAIT(2);
        __syncthreads();
        if (it + 3 < NITER) ISSUE(it + 3);
        CP_COMMIT();

        uint32_t st = sbase + (it & 3) * STAGEB;
        uint32_t ab = st + aoff, bb = st + boff;
        #pragma unroll
        for (int kk = 0; kk < 2; kk++) {
            uint32_t af[4][4], bf[2][4];
            #pragma unroll
            for (int mt = 0; mt < 4; mt++)
                ldsm_x4(af[mt], ab + kk * 32 + mt * (16 * ROWB));
            ldsm_x4(bf[0], bb + kk * 32);
            ldsm_x4(bf[1], bb + kk * 32 + 16 * ROWB);
            #pragma unroll
            for (int mt = 0; mt < 4; mt++)
                #pragma unroll
                for (int nt = 0; nt < 4; nt++)
                    mma16816(acc[mt][nt], af[mt], &bf[nt >> 1][(nt & 1) * 2]);
        }
    }

    CP_WAIT(0);
    __syncthreads();
    int* tjs = (int*)sm;
    if (tid < 128) tjs[tid] = g_tgt[col0 + tid];
    __syncthreads();

    const float NEGINF = __int_as_float(0xff800000);
    #pragma unroll
    for (int mt = 0; mt < 4; mt++) {
        int r = row0 + warpM * 64 + mt * 16 + (lane >> 2);
        int ti0 = g_tgt[r], ti1 = g_tgt[r + 8];
        float* C0 = C + (size_t)r * BN_;
        #pragma unroll
        for (int nt = 0; nt < 4; nt++) {
            int cl = warpN * 32 + nt * 8 + (lane & 3) * 2;
            int tj0 = tjs[cl], tj1 = tjs[cl + 1];
            float2 v0, v1;
            v0.x = (ti0 == tj0) ? NEGINF : acc[mt][nt][0];
            v0.y = (ti0 == tj1) ? NEGINF : acc[mt][nt][1];
            v1.x = (ti1 == tj0) ? NEGINF : acc[mt][nt][2];
            v1.y = (ti1 == tj1) ? NEGINF : acc[mt][nt][3];
            *(float2*)(C0 + col0 + cl) = v0;
            *(float2*)(C0 + 8 * BN_ + col0 + cl) = v1;
        }
    }
    #undef ISSUE
}

// ---------------- per-row exact top-k radix select + logsumexp ---------------
__device__ __forceinline__ unsigned f2key(float v) {
    unsigned b = __float_as_uint(v);
    return (b & 0x80000000u) ? ~b : (b | 0x80000000u);
}
__device__ __forceinline__ float key2f(unsigned k) {
    unsigned b = (k & 0x80000000u) ? (k ^ 0x80000000u) : ~k;
    return __uint_as_float(b);
}

__global__ void __launch_bounds__(256) rowloss_k() {
    int row = blockIdx.x;
    __shared__ unsigned sk[2][BN_];
    __shared__ unsigned hist[256];
    __shared__ float redf[8];
    __shared__ unsigned s_T;
    __shared__ int s_krem;
    __shared__ unsigned s_maxkey;
    __shared__ float s_sum[2];

    int tid = threadIdx.x;
    if (tid == 0) s_maxkey = 0;
    __syncthreads();

    unsigned lmax = 0;
    #pragma unroll
    for (int mat = 0; mat < 2; mat++) {
        const float* R = g_S[mat] + (size_t)row * BN_;
        for (int j = tid; j < BN_; j += 256) {
            unsigned k = f2key(R[j]);
            sk[mat][j] = k;
            lmax = max(lmax, k);
        }
    }
    atomicMax(&s_maxkey, lmax);
    __syncthreads();

    float pos = g_pos[row];
    float m = fmaxf(pos, key2f(s_maxkey));

    for (int mat = 0; mat < 2; mat++) {
        unsigned prefix = 0, maskv = 0;
        int krem = KTOP;
        #pragma unroll
        for (int pass = 0; pass < 4; pass++) {
            int shift = 24 - 8 * pass;
            hist[tid] = 0;
            __syncthreads();
            for (int j = tid; j < BN_; j += 256) {
                unsigned k = sk[mat][j];
                if ((k & maskv) == prefix) atomicAdd(&hist[(k >> shift) & 255u], 1u);
            }
            __syncthreads();
            if (tid == 0) {
                int cum = 0, d = 255;
                for (; d >= 0; d--) { cum += (int)hist[d]; if (cum >= krem) break; }
                s_T = prefix | ((unsigned)d << shift);
                s_krem = krem - (cum - (int)hist[d]);
            }
            __syncthreads();
            prefix = s_T;
            maskv |= (0xFFu << shift);
            krem = s_krem;
        }
        unsigned T = prefix;
        int ties = krem;

        float local = 0.f;
        for (int j = tid; j < BN_; j += 256) {
            unsigned k = sk[mat][j];
            if (k > T) local += __expf(100.f * (key2f(k) - m));
        }
        #pragma unroll
        for (int o = 16; o; o >>= 1) local += __shfl_xor_sync(0xffffffffu, local, o);
        if ((tid & 31) == 0) redf[tid >> 5] = local;
        __syncthreads();
        if (tid < 8) {
            float t = redf[tid];
            #pragma unroll
            for (int o = 4; o; o >>= 1) t += __shfl_xor_sync(0xffu, t, o);
            if (tid == 0)
                s_sum[mat] = t + (float)ties * __expf(100.f * (key2f(T) - m));
        }
        __syncthreads();
    }

    if (tid == 0) {
        float tot = __expf(100.f * (pos - m)) + s_sum[0] + s_sum[1];
        g_rowloss[row] = 100.f * m + logf(tot) - 100.f * pos;
    }
}

// ---------------- final mean reduction ---------------------------------------
__global__ void finalize_k(float* __restrict__ out) {
    float s = 0.f;
    for (int j = threadIdx.x; j < BN_; j += 1024) s += g_rowloss[j];
    #pragma unroll
    for (int o = 16; o; o >>= 1) s += __shfl_xor_sync(0xffffffffu, s, o);
    __shared__ float red[32];
    int w = threadIdx.x >> 5, l = threadIdx.x & 31;
    if (l == 0) red[w] = s;
    __syncthreads();
    if (w == 0) {
        float t = red[l];
        #pragma unroll
        for (int o = 16; o; o >>= 1) t += __shfl_xor_sync(0xffffffffu, t, o);
        if (l == 0) out[0] = t * (1.0f / (float)BN_);
    }
}

// ---------------- launch ------------------------------------------------------
extern "C" void kernel_launch(void* const* d_in, const int* in_sizes, int n_in,
                              void* d_out, int out_size) {
    const float* feat     = (const float*)d_in[0];
    const float* feat_old = (const float*)d_in[1];
    const int*   tgt_raw  = (const int*)d_in[2];
    float* out = (float*)d_out;

    cudaFuncSetAttribute(gemm_mma_k, cudaFuncAttributeMaxDynamicSharedMemorySize,
                         GEMM_SMEM);

    extract_targets_k<<<1, 1024>>>(tgt_raw);
    normalize_k<<<BN_, 128>>>(feat, 0);
    normalize_k<<<BN_, 128>>>(feat_old, 1);
    pos_k<<<BN_, 128>>>();
    dim3 grid(BN_ / 128, BN_ / 128, 2);
    gemm_mma_k<<<grid, 256, GEMM_SMEM>>>();
    rowloss_k<<<BN_, 256>>>();
    finalize_k<<<1, 1024>>>(out);
}

// round 4
// speedup vs baseline: 3.5291x; 1.6012x over previous
#include <cuda_runtime.h>
#include <cuda_fp16.h>
#include <math.h>
#include <stdint.h>

#define BN_ 4096
#define DN_ 512
#define KTOP 1024
#define KEFF 1024                 // 2 fp16-split terms x 512

// ---------------- scratch (device globals; allocation-free kernel_launch) ----
__device__ float g_fn[BN_ * DN_];            // normalized feat        (8 MB)
__device__ float g_fo[BN_ * DN_];            // normalized feat_old    (8 MB)
__device__ float g_S[2][(size_t)BN_ * BN_];  // 0: fn@fo^T  1: fn@fn^T (134 MB)
__device__ __half g_An[(size_t)BN_ * KEFF];  // [fnh|fnl]  (8 MB)
__device__ __half g_Bn[(size_t)BN_ * KEFF];  // [fnh|fnh]  (8 MB)
__device__ __half g_Bo[(size_t)BN_ * KEFF];  // [foh|foh]  (8 MB)
__device__ float g_pos[BN_];
__device__ float g_rowloss[BN_];
__device__ int   g_tgt[BN_];

// ================= small PTX helpers (sm_100-safe) ===========================
__device__ __forceinline__ uint32_t smem_u32(const void* p) {
    uint32_t a;
    asm("{ .reg .u64 t; cvta.to.shared.u64 t, %1; cvt.u32.u64 %0, t; }"
        : "=r"(a) : "l"(p));
    return a;
}
__device__ __forceinline__ void cp16(uint32_t dst, const void* src) {
    asm volatile("cp.async.cg.shared.global [%0], [%1], 16;" :: "r"(dst), "l"(src));
}
#define CP_COMMIT() asm volatile("cp.async.commit_group;" ::: "memory")
#define CP_WAIT(n)  asm volatile("cp.async.wait_group %0;" :: "n"(n) : "memory")

__device__ __forceinline__ void ldsm_x4(uint32_t* r, uint32_t addr) {
    asm volatile("ldmatrix.sync.aligned.m8n8.x4.shared.b16 {%0,%1,%2,%3}, [%4];"
                 : "=r"(r[0]), "=r"(r[1]), "=r"(r[2]), "=r"(r[3]) : "r"(addr));
}
__device__ __forceinline__ void mma16816(float* c, const uint32_t* a, const uint32_t* b) {
    asm volatile(
        "mma.sync.aligned.m16n8k16.row.col.f32.f16.f16.f32 "
        "{%0,%1,%2,%3}, {%4,%5,%6,%7}, {%8,%9}, {%0,%1,%2,%3};"
        : "+f"(c[0]), "+f"(c[1]), "+f"(c[2]), "+f"(c[3])
        : "r"(a[0]), "r"(a[1]), "r"(a[2]), "r"(a[3]), "r"(b[0]), "r"(b[1]));
}

// ---------------- targets: detect int64 vs int32, extract to int32 ----------
__global__ void extract_targets_k(const int* __restrict__ raw) {
    __shared__ int s_any;
    if (threadIdx.x == 0) s_any = 0;
    __syncthreads();
    int local = 0;
    for (int j = threadIdx.x; j < BN_; j += blockDim.x)
        if ((j & 1) && raw[j] != 0) local = 1;
    if (local) atomicOr(&s_any, 1);
    __syncthreads();
    int is64 = (s_any == 0);
    for (int j = threadIdx.x; j < BN_; j += blockDim.x)
        g_tgt[j] = is64 ? raw[2 * j] : raw[j];
}

// ---------------- L2 normalize rows + fp16 hi/lo split -----------------------
__global__ void normalize_k(const float* __restrict__ in, int which) {
    int row = blockIdx.x;
    const float* x = in + (size_t)row * DN_;
    float* outf = (which ? g_fo : g_fn) + (size_t)row * DN_;

    float s = 0.f;
    for (int j = threadIdx.x; j < DN_; j += blockDim.x) { float v = x[j]; s += v * v; }
    #pragma unroll
    for (int o = 16; o; o >>= 1) s += __shfl_xor_sync(0xffffffffu, s, o);
    __shared__ float red[4];
    int w = threadIdx.x >> 5, l = threadIdx.x & 31;
    if (l == 0) red[w] = s;
    __syncthreads();
    if (w == 0) {
        float t = (l < 4) ? red[l] : 0.f;
        #pragma unroll
        for (int o = 2; o; o >>= 1) t += __shfl_xor_sync(0xffffffffu, t, o);
        if (l == 0) red[0] = t;
    }
    __syncthreads();
    float inv = 1.f / fmaxf(sqrtf(red[0]), 1e-12f);

    for (int j = threadIdx.x; j < DN_; j += blockDim.x) {
        float v = x[j] * inv;
        outf[j] = v;
        __half h = __float2half_rn(v);
        if (which == 0) {                     // fn -> A=[h|l], Bn=[h|h]
            __half lo = __float2half_rn(v - __half2float(h));
            __half* A = g_An + (size_t)row * KEFF;
            __half* B = g_Bn + (size_t)row * KEFF;
            A[j] = h; A[j + DN_] = lo;
            B[j] = h; B[j + DN_] = h;
        } else {                              // fo -> Bo=[h|h]
            __half* B = g_Bo + (size_t)row * KEFF;
            B[j] = h; B[j + DN_] = h;
        }
    }
}

// ---------------- positive logit: diag of fn@fo^T ----------------------------
__global__ void pos_k() {
    int row = blockIdx.x;
    const float* a = g_fn + (size_t)row * DN_;
    const float* b = g_fo + (size_t)row * DN_;
    float s = 0.f;
    for (int j = threadIdx.x; j < DN_; j += blockDim.x) s += a[j] * b[j];
    #pragma unroll
    for (int o = 16; o; o >>= 1) s += __shfl_xor_sync(0xffffffffu, s, o);
    __shared__ float red[4];
    int w = threadIdx.x >> 5, l = threadIdx.x & 31;
    if (l == 0) red[w] = s;
    __syncthreads();
    if (w == 0) {
        float t = (l < 4) ? red[l] : 0.f;
        #pragma unroll
        for (int o = 2; o; o >>= 1) t += __shfl_xor_sync(0xffffffffu, t, o);
        if (l == 0) g_pos[row] = t;
    }
}

// ================= mma.sync fp16 GEMM: S = A(4096x1024) x B^T ================
// CTA tile 128x128, warp grid 2x4 (warp tile 64x32), KC=32, 4-slot cp.async.
#define KC 32
#define NITER (KEFF / KC)          // 32
#define ROWB 80                    // 64B data + 16B pad (conflict-free ldmatrix)
#define ATILE (128 * ROWB)         // 10240
#define STAGEB (2 * ATILE)         // 20480
#define GEMM_SMEM (4 * STAGEB)     // 81920

__global__ void __launch_bounds__(256) gemm_mma_k() {
    extern __shared__ char sm[];
    uint32_t sbase = smem_u32(sm);

    int tid = threadIdx.x, wid = tid >> 5, lane = tid & 31;
    int warpM = wid >> 2, warpN = wid & 3;
    int mat = blockIdx.z;
    const __half* Ag = g_An;
    const __half* Bg = mat ? g_Bn : g_Bo;
    float* C = g_S[mat];
    int row0 = blockIdx.y * 128, col0 = blockIdx.x * 128;

    int sA0 = tid, sA1 = tid + 256, sB0 = tid, sB1 = tid + 256;
    int rA0 = sA0 >> 2, gA0 = sA0 & 3, rA1 = sA1 >> 2, gA1 = sA1 & 3;
    int rB0 = sB0 >> 2, gB0 = sB0 & 3, rB1 = sB1 >> 2, gB1 = sB1 & 3;
    const char* pA0 = (const char*)(Ag + (size_t)(row0 + rA0) * KEFF) + gA0 * 16;
    const char* pA1 = (const char*)(Ag + (size_t)(row0 + rA1) * KEFF) + gA1 * 16;
    const char* pB0 = (const char*)(Bg + (size_t)(col0 + rB0) * KEFF) + gB0 * 16;
    const char* pB1 = (const char*)(Bg + (size_t)(col0 + rB1) * KEFF) + gB1 * 16;
    uint32_t dA0 = rA0 * ROWB + gA0 * 16, dA1 = rA1 * ROWB + gA1 * 16;
    uint32_t dB0 = ATILE + rB0 * ROWB + gB0 * 16, dB1 = ATILE + rB1 * ROWB + gB1 * 16;

    #define ISSUE(it) do {                                                     \
        uint32_t st = sbase + ((it) & 3) * STAGEB;                             \
        int ko = (it) * 64;                                                    \
        cp16(st + dA0, pA0 + ko); cp16(st + dA1, pA1 + ko);                    \
        cp16(st + dB0, pB0 + ko); cp16(st + dB1, pB1 + ko);                    \
    } while (0)

    ISSUE(0); CP_COMMIT();
    ISSUE(1); CP_COMMIT();
    ISSUE(2); CP_COMMIT();

    float acc[4][4][4] = {};
    uint32_t aoff = (uint32_t)((warpM * 64 + (lane & 15)) * ROWB + (lane >> 4) * 16);
    uint32_t boff = (uint32_t)(ATILE +
        (warpN * 32 + (lane & 7) + (lane >> 4) * 8) * ROWB + ((lane >> 3) & 1) * 16);

    for (int it = 0; it < NITER; it++) {
        CP_WAIT(2);
        __syncthreads();
        if (it + 3 < NITER) ISSUE(it + 3);
        CP_COMMIT();

        uint32_t st = sbase + (it & 3) * STAGEB;
        uint32_t ab = st + aoff, bb = st + boff;
        #pragma unroll
        for (int kk = 0; kk < 2; kk++) {
            uint32_t af[4][4], bf[2][4];
            #pragma unroll
            for (int mt = 0; mt < 4; mt++)
                ldsm_x4(af[mt], ab + kk * 32 + mt * (16 * ROWB));
            ldsm_x4(bf[0], bb + kk * 32);
            ldsm_x4(bf[1], bb + kk * 32 + 16 * ROWB);
            #pragma unroll
            for (int mt = 0; mt < 4; mt++)
                #pragma unroll
                for (int nt = 0; nt < 4; nt++)
                    mma16816(acc[mt][nt], af[mt], &bf[nt >> 1][(nt & 1) * 2]);
        }
    }

    CP_WAIT(0);
    __syncthreads();
    int* tjs = (int*)sm;
    if (tid < 128) tjs[tid] = g_tgt[col0 + tid];
    __syncthreads();

    const float NEGINF = __int_as_float(0xff800000);
    #pragma unroll
    for (int mt = 0; mt < 4; mt++) {
        int r = row0 + warpM * 64 + mt * 16 + (lane >> 2);
        int ti0 = g_tgt[r], ti1 = g_tgt[r + 8];
        float* C0 = C + (size_t)r * BN_;
        #pragma unroll
        for (int nt = 0; nt < 4; nt++) {
            int cl = warpN * 32 + nt * 8 + (lane & 3) * 2;
            int tj0 = tjs[cl], tj1 = tjs[cl + 1];
            float2 v0, v1;
            v0.x = (ti0 == tj0) ? NEGINF : acc[mt][nt][0];
            v0.y = (ti0 == tj1) ? NEGINF : acc[mt][nt][1];
            v1.x = (ti1 == tj0) ? NEGINF : acc[mt][nt][2];
            v1.y = (ti1 == tj1) ? NEGINF : acc[mt][nt][3];
            *(float2*)(C0 + col0 + cl) = v0;
            *(float2*)(C0 + 8 * BN_ + col0 + cl) = v1;
        }
    }
    #undef ISSUE
}

// ================= per-row top-k via value-linear histogram select ===========
// Values are cosine sims in [-1, 1] (masked = -inf). Two-level 1024-bin select,
// then one exp sweep. Residual r2 elements valued at sub-bin midpoint
// (width 1.9e-6 cos = 1.9e-4 logit, on a ~e^-11-weight set: negligible).

// find largest bin b with suffix_count(b) >= K; out_c = count strictly above b.
__device__ __forceinline__ void suffix_find(unsigned* hist, unsigned* gs, int K,
                                            int* s_b, int* s_c, int tid) {
    __syncthreads();
    unsigned g = hist[4 * tid] + hist[4 * tid + 1] + hist[4 * tid + 2] + hist[4 * tid + 3];
    gs[tid] = g;
    __syncthreads();
    #pragma unroll
    for (int off = 1; off < 256; off <<= 1) {
        unsigned add = (tid + off < 256) ? gs[tid + off] : 0u;
        __syncthreads();
        gs[tid] += add;
        __syncthreads();
    }
    unsigned Ft = gs[tid];
    unsigned Ftn = (tid < 255) ? gs[tid + 1] : 0u;
    if (Ft >= (unsigned)K && Ftn < (unsigned)K) {
        unsigned F = Ftn;
        #pragma unroll
        for (int j = 3; j >= 0; j--) {
            unsigned Fb = F + hist[4 * tid + j];
            if (Fb >= (unsigned)K) { *s_b = 4 * tid + j; *s_c = (int)F; break; }
            F = Fb;
        }
    }
    __syncthreads();
}

__device__ __forceinline__ int val_bin(float v) {
    return min(1023, max(0, (int)((v + 1.0f) * 512.0f)));
}

__global__ void __launch_bounds__(256) rowloss_k() {
    __shared__ float vals[BN_];
    __shared__ unsigned hist[1024];
    __shared__ unsigned gs[256];
    __shared__ int s_b, s_c, s_b2, s_c2;
    __shared__ float s_m[2], s_S[2], redf[8];

    int row = blockIdx.x, tid = threadIdx.x;

    for (int mat = 0; mat < 2; mat++) {
        const float* R = g_S[mat] + (size_t)row * BN_;
        #pragma unroll
        for (int j = 0; j < 4; j++) hist[4 * tid + j] = 0;
        __syncthreads();

        float lmax = -1e30f;
        for (int j = tid; j < BN_; j += 256) {
            float v = R[j];
            vals[j] = v;
            lmax = fmaxf(lmax, v);
            atomicAdd(&hist[val_bin(v)], 1u);
        }
        #pragma unroll
        for (int o = 16; o; o >>= 1) lmax = fmaxf(lmax, __shfl_xor_sync(0xffffffffu, lmax, o));
        if ((tid & 31) == 0) redf[tid >> 5] = lmax;
        __syncthreads();
        if (tid == 0) {
            float m = redf[0];
            #pragma unroll
            for (int w = 1; w < 8; w++) m = fmaxf(m, redf[w]);
            s_m[mat] = m;
        }

        suffix_find(hist, gs, KTOP, &s_b, &s_c, tid);
        int b1 = s_b;
        int r1 = KTOP - s_c;
        float lo = (float)b1 * (1.0f / 512.0f) - 1.0f;

        // refine within boundary bin: 1024 sub-bins
        #pragma unroll
        for (int j = 0; j < 4; j++) hist[4 * tid + j] = 0;
        __syncthreads();
        for (int j = tid; j < BN_; j += 256) {
            float v = vals[j];
            if (val_bin(v) == b1) {
                int sb = min(1023, max(0, (int)((v - lo) * (512.0f * 1024.0f))));
                atomicAdd(&hist[sb], 1u);
            }
        }
        suffix_find(hist, gs, r1, &s_b2, &s_c2, tid);
        int b2 = s_b2;
        int r2 = r1 - s_c2;
        float m = s_m[mat];

        // final exp sweep over selected elements
        float local = 0.f;
        for (int j = tid; j < BN_; j += 256) {
            float v = vals[j];
            int b = val_bin(v);
            bool take = (b > b1);
            if (b == b1) {
                int sb = min(1023, max(0, (int)((v - lo) * (512.0f * 1024.0f))));
                take = (sb > b2);
            }
            if (take) local += __expf(100.f * (v - m));
        }
        #pragma unroll
        for (int o = 16; o; o >>= 1) local += __shfl_xor_sync(0xffffffffu, local, o);
        if ((tid & 31) == 0) redf[tid >> 5] = local;
        __syncthreads();
        if (tid == 0) {
            float t = 0.f;
            #pragma unroll
            for (int w = 0; w < 8; w++) t += redf[w];
            float submid = lo + ((float)b2 + 0.5f) * (1.0f / (512.0f * 1024.0f));
            s_S[mat] = t + (float)r2 * __expf(100.f * (submid - m));
        }
        __syncthreads();
    }

    if (tid == 0) {
        float pos = g_pos[row];
        float M = fmaxf(fmaxf(s_m[0], s_m[1]), pos);
        float tot = __expf(100.f * (pos - M)) +
                    s_S[0] * __expf(100.f * (s_m[0] - M)) +
                    s_S[1] * __expf(100.f * (s_m[1] - M));
        g_rowloss[row] = 100.f * M + logf(tot) - 100.f * pos;
    }
}

// ---------------- final mean reduction ---------------------------------------
__global__ void finalize_k(float* __restrict__ out) {
    float s = 0.f;
    for (int j = threadIdx.x; j < BN_; j += 1024) s += g_rowloss[j];
    #pragma unroll
    for (int o = 16; o; o >>= 1) s += __shfl_xor_sync(0xffffffffu, s, o);
    __shared__ float red[32];
    int w = threadIdx.x >> 5, l = threadIdx.x & 31;
    if (l == 0) red[w] = s;
    __syncthreads();
    if (w == 0) {
        float t = red[l];
        #pragma unroll
        for (int o = 16; o; o >>= 1) t += __shfl_xor_sync(0xffffffffu, t, o);
        if (l == 0) out[0] = t * (1.0f / (float)BN_);
    }
}

// ---------------- launch ------------------------------------------------------
extern "C" void kernel_launch(void* const* d_in, const int* in_sizes, int n_in,
                              void* d_out, int out_size) {
    const float* feat     = (const float*)d_in[0];
    const float* feat_old = (const float*)d_in[1];
    const int*   tgt_raw  = (const int*)d_in[2];
    float* out = (float*)d_out;

    cudaFuncSetAttribute(gemm_mma_k, cudaFuncAttributeMaxDynamicSharedMemorySize,
                         GEMM_SMEM);

    extract_targets_k<<<1, 1024>>>(tgt_raw);
    normalize_k<<<BN_, 128>>>(feat, 0);
    normalize_k<<<BN_, 128>>>(feat_old, 1);
    pos_k<<<BN_, 128>>>();
    dim3 grid(BN_ / 128, BN_ / 128, 2);
    gemm_mma_k<<<grid, 256, GEMM_SMEM>>>();
    rowloss_k<<<BN_, 256>>>();
    finalize_k<<<1, 1024>>>(out);
}

// round 5
// speedup vs baseline: 6.4266x; 1.8211x over previous
#include <cuda_runtime.h>
#include <cuda_fp16.h>
#include <math.h>
#include <stdint.h>

#define BN_ 4096
#define DN_ 512
#define KTOP 1024
#define KEFF 512                  // pure fp16 single-term GEMM

// ---------------- scratch (device globals; allocation-free kernel_launch) ----
__device__ float g_fn[BN_ * DN_];            // normalized feat        (8 MB)
__device__ float g_fo[BN_ * DN_];            // normalized feat_old    (8 MB)
__device__ float g_S[2][(size_t)BN_ * BN_];  // 0: fn@fo^T  1: fn@fn^T (134 MB)
__device__ __half g_Ah[(size_t)BN_ * KEFF];  // fnh  (4 MB) — A for both mats, B for mat1
__device__ __half g_Bo[(size_t)BN_ * KEFF];  // foh  (4 MB) — B for mat0
__device__ float g_pos[BN_];
__device__ float g_rowloss[BN_];
__device__ int   g_tgt[BN_];

// ================= small PTX helpers (sm_100-safe) ===========================
__device__ __forceinline__ uint32_t smem_u32(const void* p) {
    uint32_t a;
    asm("{ .reg .u64 t; cvta.to.shared.u64 t, %1; cvt.u32.u64 %0, t; }"
        : "=r"(a) : "l"(p));
    return a;
}
__device__ __forceinline__ void cp16(uint32_t dst, const void* src) {
    asm volatile("cp.async.cg.shared.global [%0], [%1], 16;" :: "r"(dst), "l"(src));
}
#define CP_COMMIT() asm volatile("cp.async.commit_group;" ::: "memory")
#define CP_WAIT(n)  asm volatile("cp.async.wait_group %0;" :: "n"(n) : "memory")

__device__ __forceinline__ void ldsm_x4(uint32_t* r, uint32_t addr) {
    asm volatile("ldmatrix.sync.aligned.m8n8.x4.shared.b16 {%0,%1,%2,%3}, [%4];"
                 : "=r"(r[0]), "=r"(r[1]), "=r"(r[2]), "=r"(r[3]) : "r"(addr));
}
__device__ __forceinline__ void mma16816(float* c, const uint32_t* a, const uint32_t* b) {
    asm volatile(
        "mma.sync.aligned.m16n8k16.row.col.f32.f16.f16.f32 "
        "{%0,%1,%2,%3}, {%4,%5,%6,%7}, {%8,%9}, {%0,%1,%2,%3};"
        : "+f"(c[0]), "+f"(c[1]), "+f"(c[2]), "+f"(c[3])
        : "r"(a[0]), "r"(a[1]), "r"(a[2]), "r"(a[3]), "r"(b[0]), "r"(b[1]));
}

// ---------------- targets: detect int64 vs int32, extract to int32 ----------
__global__ void extract_targets_k(const int* __restrict__ raw) {
    __shared__ int s_any;
    if (threadIdx.x == 0) s_any = 0;
    __syncthreads();
    int local = 0;
    for (int j = threadIdx.x; j < BN_; j += blockDim.x)
        if ((j & 1) && raw[j] != 0) local = 1;
    if (local) atomicOr(&s_any, 1);
    __syncthreads();
    int is64 = (s_any == 0);
    for (int j = threadIdx.x; j < BN_; j += blockDim.x)
        g_tgt[j] = is64 ? raw[2 * j] : raw[j];
}

// ---------------- L2 normalize rows + fp16 cast ------------------------------
__global__ void normalize_k(const float* __restrict__ in, int which) {
    int row = blockIdx.x;
    const float* x = in + (size_t)row * DN_;
    float* outf = (which ? g_fo : g_fn) + (size_t)row * DN_;
    __half* outh = (which ? g_Bo : g_Ah) + (size_t)row * KEFF;

    float s = 0.f;
    for (int j = threadIdx.x; j < DN_; j += blockDim.x) { float v = x[j]; s += v * v; }
    #pragma unroll
    for (int o = 16; o; o >>= 1) s += __shfl_xor_sync(0xffffffffu, s, o);
    __shared__ float red[4];
    int w = threadIdx.x >> 5, l = threadIdx.x & 31;
    if (l == 0) red[w] = s;
    __syncthreads();
    if (w == 0) {
        float t = (l < 4) ? red[l] : 0.f;
        #pragma unroll
        for (int o = 2; o; o >>= 1) t += __shfl_xor_sync(0xffffffffu, t, o);
        if (l == 0) red[0] = t;
    }
    __syncthreads();
    float inv = 1.f / fmaxf(sqrtf(red[0]), 1e-12f);

    for (int j = threadIdx.x; j < DN_; j += blockDim.x) {
        float v = x[j] * inv;
        outf[j] = v;
        outh[j] = __float2half_rn(v);
    }
}

// ---------------- positive logit: diag of fn@fo^T (exact fp32) ---------------
__global__ void pos_k() {
    int row = blockIdx.x;
    const float* a = g_fn + (size_t)row * DN_;
    const float* b = g_fo + (size_t)row * DN_;
    float s = 0.f;
    for (int j = threadIdx.x; j < DN_; j += blockDim.x) s += a[j] * b[j];
    #pragma unroll
    for (int o = 16; o; o >>= 1) s += __shfl_xor_sync(0xffffffffu, s, o);
    __shared__ float red[4];
    int w = threadIdx.x >> 5, l = threadIdx.x & 31;
    if (l == 0) red[w] = s;
    __syncthreads();
    if (w == 0) {
        float t = (l < 4) ? red[l] : 0.f;
        #pragma unroll
        for (int o = 2; o; o >>= 1) t += __shfl_xor_sync(0xffffffffu, t, o);
        if (l == 0) g_pos[row] = t;
    }
}

// ================= mma.sync fp16 GEMM: S = A(4096x512) x B^T =================
// CTA tile 128x128, warp grid 2x4 (warp tile 64x32), KC=32, 4-slot cp.async.
#define KC 32
#define NITER (KEFF / KC)          // 16
#define ROWB 80                    // 64B data + 16B pad (conflict-free ldmatrix)
#define ATILE (128 * ROWB)         // 10240
#define STAGEB (2 * ATILE)         // 20480
#define GEMM_SMEM (4 * STAGEB)     // 81920

__global__ void __launch_bounds__(256, 2) gemm_mma_k() {
    extern __shared__ char sm[];
    uint32_t sbase = smem_u32(sm);

    int tid = threadIdx.x, wid = tid >> 5, lane = tid & 31;
    int warpM = wid >> 2, warpN = wid & 3;
    int mat = blockIdx.z;
    const __half* Ag = g_Ah;
    const __half* Bg = mat ? g_Ah : g_Bo;
    float* C = g_S[mat];
    int row0 = blockIdx.y * 128, col0 = blockIdx.x * 128;

    int rA0 = tid >> 2, gA0 = tid & 3, rA1 = (tid + 256) >> 2, gA1 = tid & 3;
    const char* pA0 = (const char*)(Ag + (size_t)(row0 + rA0) * KEFF) + gA0 * 16;
    const char* pA1 = (const char*)(Ag + (size_t)(row0 + rA1) * KEFF) + gA1 * 16;
    const char* pB0 = (const char*)(Bg + (size_t)(col0 + rA0) * KEFF) + gA0 * 16;
    const char* pB1 = (const char*)(Bg + (size_t)(col0 + rA1) * KEFF) + gA1 * 16;
    uint32_t dA0 = rA0 * ROWB + gA0 * 16, dA1 = rA1 * ROWB + gA1 * 16;
    uint32_t dB0 = ATILE + dA0, dB1 = ATILE + dA1;

    #define ISSUE(it) do {                                                     \
        uint32_t st = sbase + ((it) & 3) * STAGEB;                             \
        int ko = (it) * 64;                                                    \
        cp16(st + dA0, pA0 + ko); cp16(st + dA1, pA1 + ko);                    \
        cp16(st + dB0, pB0 + ko); cp16(st + dB1, pB1 + ko);                    \
    } while (0)

    ISSUE(0); CP_COMMIT();
    ISSUE(1); CP_COMMIT();
    ISSUE(2); CP_COMMIT();

    float acc[4][4][4] = {};
    uint32_t aoff = (uint32_t)((warpM * 64 + (lane & 15)) * ROWB + (lane >> 4) * 16);
    uint32_t boff = (uint32_t)(ATILE +
        (warpN * 32 + (lane & 7) + (lane >> 4) * 8) * ROWB + ((lane >> 3) & 1) * 16);

    for (int it = 0; it < NITER; it++) {
        CP_WAIT(2);
        __syncthreads();
        if (it + 3 < NITER) ISSUE(it + 3);
        CP_COMMIT();

        uint32_t st = sbase + (it & 3) * STAGEB;
        uint32_t ab = st + aoff, bb = st + boff;
        #pragma unroll
        for (int kk = 0; kk < 2; kk++) {
            uint32_t af[4][4], bf[2][4];
            #pragma unroll
            for (int mt = 0; mt < 4; mt++)
                ldsm_x4(af[mt], ab + kk * 32 + mt * (16 * ROWB));
            ldsm_x4(bf[0], bb + kk * 32);
            ldsm_x4(bf[1], bb + kk * 32 + 16 * ROWB);
            #pragma unroll
            for (int mt = 0; mt < 4; mt++)
                #pragma unroll
                for (int nt = 0; nt < 4; nt++)
                    mma16816(acc[mt][nt], af[mt], &bf[nt >> 1][(nt & 1) * 2]);
        }
    }

    CP_WAIT(0);
    __syncthreads();
    int* tjs = (int*)sm;
    if (tid < 128) tjs[tid] = g_tgt[col0 + tid];
    __syncthreads();

    const float NEGINF = __int_as_float(0xff800000);
    #pragma unroll
    for (int mt = 0; mt < 4; mt++) {
        int r = row0 + warpM * 64 + mt * 16 + (lane >> 2);
        int ti0 = g_tgt[r], ti1 = g_tgt[r + 8];
        float* C0 = C + (size_t)r * BN_;
        #pragma unroll
        for (int nt = 0; nt < 4; nt++) {
            int cl = warpN * 32 + nt * 8 + (lane & 3) * 2;
            int tj0 = tjs[cl], tj1 = tjs[cl + 1];
            float2 v0, v1;
            v0.x = (ti0 == tj0) ? NEGINF : acc[mt][nt][0];
            v0.y = (ti0 == tj1) ? NEGINF : acc[mt][nt][1];
            v1.x = (ti1 == tj0) ? NEGINF : acc[mt][nt][2];
            v1.y = (ti1 == tj1) ? NEGINF : acc[mt][nt][3];
            *(float2*)(C0 + col0 + cl) = v0;
            *(float2*)(C0 + 8 * BN_ + col0 + cl) = v1;
        }
    }
    #undef ISSUE
}

// ================= per-row top-k via one-level value histogram ===============
// Cos sims in [-1, 1]; 1024 linear bins. Boundary-bin residual valued at bin
// midpoint (width 0.195 logit, total residual weight ~1e-4 of S: ~1e-5 error).
__device__ __forceinline__ int val_bin(float v) {
    return min(1023, max(0, (int)((v + 1.0f) * 512.0f)));
}

__global__ void __launch_bounds__(256) rowloss_k() {
    __shared__ float vals[BN_];
    __shared__ unsigned hist[1024];
    __shared__ unsigned ws[8];
    __shared__ int s_b, s_c;
    __shared__ float s_m[2], s_S[2], redf[8];

    int row = blockIdx.x, tid = threadIdx.x;
    int lane = tid & 31, warp = tid >> 5;

    for (int mat = 0; mat < 2; mat++) {
        const float4* R4 = (const float4*)(g_S[mat] + (size_t)row * BN_);
        #pragma unroll
        for (int j = 0; j < 4; j++) hist[4 * tid + j] = 0;
        __syncthreads();

        float lmax = -1e30f;
        #pragma unroll
        for (int q = 0; q < 4; q++) {
            int j = tid + q * 256;
            float4 v = R4[j];
            *(float4*)(vals + 4 * j) = v;
            lmax = fmaxf(fmaxf(lmax, fmaxf(v.x, v.y)), fmaxf(v.z, v.w));
            atomicAdd(&hist[val_bin(v.x)], 1u);
            atomicAdd(&hist[val_bin(v.y)], 1u);
            atomicAdd(&hist[val_bin(v.z)], 1u);
            atomicAdd(&hist[val_bin(v.w)], 1u);
        }
        #pragma unroll
        for (int o = 16; o; o >>= 1)
            lmax = fmaxf(lmax, __shfl_xor_sync(0xffffffffu, lmax, o));
        if (lane == 0) redf[warp] = lmax;
        __syncthreads();

        // ---- suffix scan over 1024 bins (4 bins/thread, shfl warp scan) ----
        unsigned h0 = hist[4 * tid], h1 = hist[4 * tid + 1],
                 h2 = hist[4 * tid + 2], h3 = hist[4 * tid + 3];
        unsigned g = h0 + h1 + h2 + h3;
        unsigned v = g;
        #pragma unroll
        for (int off = 1; off < 32; off <<= 1) {
            unsigned u = __shfl_down_sync(0xffffffffu, v, off);
            if (lane + off < 32) v += u;
        }
        if (lane == 0) ws[warp] = v;      // warp total
        unsigned vin = __shfl_sync(0xffffffffu, v, 0);  // keep v per-thread
        (void)vin;
        __syncthreads();
        unsigned later = 0;
        #pragma unroll
        for (int w2 = 0; w2 < 8; w2++) if (w2 > warp) later += ws[w2];
        unsigned F_t = v + later;          // suffix incl. this thread's 4 bins

        if (F_t >= (unsigned)KTOP && F_t - g < (unsigned)KTOP) {
            unsigned F = F_t - g;          // count strictly above this group
            if (F + h3 >= (unsigned)KTOP) { s_b = 4 * tid + 3; s_c = (int)F; }
            else {
                F += h3;
                if (F + h2 >= (unsigned)KTOP) { s_b = 4 * tid + 2; s_c = (int)F; }
                else {
                    F += h2;
                    if (F + h1 >= (unsigned)KTOP) { s_b = 4 * tid + 1; s_c = (int)F; }
                    else { s_b = 4 * tid; s_c = (int)(F + h1); }
                }
            }
        }
        __syncthreads();

        int b1 = s_b;
        int r1 = KTOP - s_c;               // residual taken from boundary bin
        float m;
        {
            float t = redf[0];
            #pragma unroll
            for (int w2 = 1; w2 < 8; w2++) t = fmaxf(t, redf[w2]);
            m = t;
        }

        // ---- exp sweep over selected elements ----
        float local = 0.f;
        #pragma unroll
        for (int q = 0; q < 4; q++) {
            int j = tid + q * 256;
            float4 vv = *(const float4*)(vals + 4 * j);
            if (val_bin(vv.x) > b1) local += __expf(100.f * (vv.x - m));
            if (val_bin(vv.y) > b1) local += __expf(100.f * (vv.y - m));
            if (val_bin(vv.z) > b1) local += __expf(100.f * (vv.z - m));
            if (val_bin(vv.w) > b1) local += __expf(100.f * (vv.w - m));
        }
        #pragma unroll
        for (int o = 16; o; o >>= 1) local += __shfl_xor_sync(0xffffffffu, local, o);
        __syncthreads();                   // redf reuse
        if (lane == 0) redf[warp] = local;
        __syncthreads();
        if (tid == 0) {
            float t = 0.f;
            #pragma unroll
            for (int w2 = 0; w2 < 8; w2++) t += redf[w2];
            float mid = ((float)b1 + 0.5f) * (1.0f / 512.0f) - 1.0f;
            s_S[mat] = t + (float)r1 * __expf(100.f * (mid - m));
            s_m[mat] = m;
        }
        __syncthreads();
    }

    if (tid == 0) {
        float pos = g_pos[row];
        float M = fmaxf(fmaxf(s_m[0], s_m[1]), pos);
        float tot = __expf(100.f * (pos - M)) +
                    s_S[0] * __expf(100.f * (s_m[0] - M)) +
                    s_S[1] * __expf(100.f * (s_m[1] - M));
        g_rowloss[row] = 100.f * M + logf(tot) - 100.f * pos;
    }
}

// ---------------- final mean reduction ---------------------------------------
__global__ void finalize_k(float* __restrict__ out) {
    float s = 0.f;
    for (int j = threadIdx.x; j < BN_; j += 1024) s += g_rowloss[j];
    #pragma unroll
    for (int o = 16; o; o >>= 1) s += __shfl_xor_sync(0xffffffffu, s, o);
    __shared__ float red[32];
    int w = threadIdx.x >> 5, l = threadIdx.x & 31;
    if (l == 0) red[w] = s;
    __syncthreads();
    if (w == 0) {
        float t = red[l];
        #pragma unroll
        for (int o = 16; o; o >>= 1) t += __shfl_xor_sync(0xffffffffu, t, o);
        if (l == 0) out[0] = t * (1.0f / (float)BN_);
    }
}

// ---------------- launch ------------------------------------------------------
extern "C" void kernel_launch(void* const* d_in, const int* in_sizes, int n_in,
                              void* d_out, int out_size) {
    const float* feat     = (const float*)d_in[0];
    const float* feat_old = (const float*)d_in[1];
    const int*   tgt_raw  = (const int*)d_in[2];
    float* out = (float*)d_out;

    cudaFuncSetAttribute(gemm_mma_k, cudaFuncAttributeMaxDynamicSharedMemorySize,
                         GEMM_SMEM);

    extract_targets_k<<<1, 1024>>>(tgt_raw);
    normalize_k<<<BN_, 128>>>(feat, 0);
    normalize_k<<<BN_, 128>>>(feat_old, 1);
    pos_k<<<BN_, 128>>>();
    dim3 grid(BN_ / 128, BN_ / 128, 2);
    gemm_mma_k<<<grid, 256, GEMM_SMEM>>>();
    rowloss_k<<<BN_, 256>>>();
    finalize_k<<<1, 1024>>>(out);
}

// round 6
// speedup vs baseline: 6.7103x; 1.0441x over previous
#include <cuda_runtime.h>
#include <cuda_fp16.h>
#include <math.h>
#include <stdint.h>

#define BN_ 4096
#define DN_ 512
#define KTOP 1024
#define KEFF 512

// ---------------- scratch (device globals; allocation-free kernel_launch) ----
__device__ __half g_S[2][(size_t)BN_ * BN_]; // 0: fn@fo^T  1: fn@fn^T (67 MB)
__device__ __half g_Ah[(size_t)BN_ * KEFF]; // fnh (4 MB) — A both mats, B for mat1
__device__ __half g_Bo[(size_t)BN_ * KEFF]; // foh (4 MB) — B for mat0
__device__ float g_pos[BN_];
__device__ float g_rowloss[BN_];
__device__ int   g_tgt[BN_];

// ================= small PTX helpers (sm_100-safe) ===========================
__device__ __forceinline__ uint32_t smem_u32(const void* p) {
    uint32_t a;
    asm("{ .reg .u64 t; cvta.to.shared.u64 t, %1; cvt.u32.u64 %0, t; }"
        : "=r"(a) : "l"(p));
    return a;
}
__device__ __forceinline__ void cp16(uint32_t dst, const void* src) {
    asm volatile("cp.async.cg.shared.global [%0], [%1], 16;" :: "r"(dst), "l"(src));
}
#define CP_COMMIT() asm volatile("cp.async.commit_group;" ::: "memory")
#define CP_WAIT(n)  asm volatile("cp.async.wait_group %0;" :: "n"(n) : "memory")

__device__ __forceinline__ void ldsm_x4(uint32_t* r, uint32_t addr) {
    asm volatile("ldmatrix.sync.aligned.m8n8.x4.shared.b16 {%0,%1,%2,%3}, [%4];"
                 : "=r"(r[0]), "=r"(r[1]), "=r"(r[2]), "=r"(r[3]) : "r"(addr));
}
__device__ __forceinline__ void mma16816(float* c, const uint32_t* a, const uint32_t* b) {
    asm volatile(
        "mma.sync.aligned.m16n8k16.row.col.f32.f16.f16.f32 "
        "{%0,%1,%2,%3}, {%4,%5,%6,%7}, {%8,%9}, {%0,%1,%2,%3};"
        : "+f"(c[0]), "+f"(c[1]), "+f"(c[2]), "+f"(c[3])
        : "r"(a[0]), "r"(a[1]), "r"(a[2]), "r"(a[3]), "r"(b[0]), "r"(b[1]));
}

// ---------------- targets: detect int64 vs int32, extract to int32 ----------
__global__ void extract_targets_k(const int* __restrict__ raw) {
    __shared__ int s_any;
    if (threadIdx.x == 0) s_any = 0;
    __syncthreads();
    int local = 0;
    for (int j = threadIdx.x; j < BN_; j += blockDim.x)
        if ((j & 1) && raw[j] != 0) local = 1;
    if (local) atomicOr(&s_any, 1);
    __syncthreads();
    int is64 = (s_any == 0);
    for (int j = threadIdx.x; j < BN_; j += blockDim.x)
        g_tgt[j] = is64 ? raw[2 * j] : raw[j];
}

// ---------------- fused prep: normalize both + fp16 cast + exact pos ---------
__global__ void prep_k(const float* __restrict__ feat,
                       const float* __restrict__ feat_old) {
    int row = blockIdx.x;
    const float* a = feat + (size_t)row * DN_;
    const float* b = feat_old + (size_t)row * DN_;

    float snn = 0.f, soo = 0.f, sno = 0.f;
    for (int j = threadIdx.x; j < DN_; j += 128) {
        float x = a[j], y = b[j];
        snn += x * x; soo += y * y; sno += x * y;
    }
    #pragma unroll
    for (int o = 16; o; o >>= 1) {
        snn += __shfl_xor_sync(0xffffffffu, snn, o);
        soo += __shfl_xor_sync(0xffffffffu, soo, o);
        sno += __shfl_xor_sync(0xffffffffu, sno, o);
    }
    __shared__ float red[3][4];
    int w = threadIdx.x >> 5, l = threadIdx.x & 31;
    if (l == 0) { red[0][w] = snn; red[1][w] = soo; red[2][w] = sno; }
    __syncthreads();
    float tn = red[0][0] + red[0][1] + red[0][2] + red[0][3];
    float to = red[1][0] + red[1][1] + red[1][2] + red[1][3];
    float tx = red[2][0] + red[2][1] + red[2][2] + red[2][3];
    float invn = 1.f / fmaxf(sqrtf(tn), 1e-12f);
    float invo = 1.f / fmaxf(sqrtf(to), 1e-12f);
    if (threadIdx.x == 0) g_pos[row] = tx * invn * invo;

    __half* An = g_Ah + (size_t)row * KEFF;
    __half* Bo = g_Bo + (size_t)row * KEFF;
    for (int j = threadIdx.x; j < DN_; j += 128) {
        An[j] = __float2half_rn(a[j] * invn);
        Bo[j] = __float2half_rn(b[j] * invo);
    }
}

// ================= mma.sync fp16 GEMM: S = A(4096x512) x B^T, half out =======
#define KC 32
#define NITER (KEFF / KC)          // 16
#define ROWB 80
#define ATILE (128 * ROWB)
#define STAGEB (2 * ATILE)
#define GEMM_SMEM (4 * STAGEB)     // 81920

__global__ void __launch_bounds__(256, 2) gemm_mma_k() {
    extern __shared__ char sm[];
    uint32_t sbase = smem_u32(sm);

    int tid = threadIdx.x, wid = tid >> 5, lane = tid & 31;
    int warpM = wid >> 2, warpN = wid & 3;
    int mat = blockIdx.z;
    const __half* Ag = g_Ah;
    const __half* Bg = mat ? g_Ah : g_Bo;
    __half* C = g_S[mat];
    int row0 = blockIdx.y * 128, col0 = blockIdx.x * 128;

    int rA0 = tid >> 2, gA0 = tid & 3, rA1 = (tid + 256) >> 2;
    const char* pA0 = (const char*)(Ag + (size_t)(row0 + rA0) * KEFF) + gA0 * 16;
    const char* pA1 = (const char*)(Ag + (size_t)(row0 + rA1) * KEFF) + gA0 * 16;
    const char* pB0 = (const char*)(Bg + (size_t)(col0 + rA0) * KEFF) + gA0 * 16;
    const char* pB1 = (const char*)(Bg + (size_t)(col0 + rA1) * KEFF) + gA0 * 16;
    uint32_t dA0 = rA0 * ROWB + gA0 * 16, dA1 = rA1 * ROWB + gA0 * 16;
    uint32_t dB0 = ATILE + dA0, dB1 = ATILE + dA1;

    #define ISSUE(it) do {                                                     \
        uint32_t st = sbase + ((it) & 3) * STAGEB;                             \
        int ko = (it) * 64;                                                    \
        cp16(st + dA0, pA0 + ko); cp16(st + dA1, pA1 + ko);                    \
        cp16(st + dB0, pB0 + ko); cp16(st + dB1, pB1 + ko);                    \
    } while (0)

    ISSUE(0); CP_COMMIT();
    ISSUE(1); CP_COMMIT();
    ISSUE(2); CP_COMMIT();

    float acc[4][4][4] = {};
    uint32_t aoff = (uint32_t)((warpM * 64 + (lane & 15)) * ROWB + (lane >> 4) * 16);
    uint32_t boff = (uint32_t)(ATILE +
        (warpN * 32 + (lane & 7) + (lane >> 4) * 8) * ROWB + ((lane >> 3) & 1) * 16);

    for (int it = 0; it < NITER; it++) {
        CP_WAIT(2);
        __syncthreads();
        if (it + 3 < NITER) ISSUE(it + 3);
        CP_COMMIT();

        uint32_t st = sbase + (it & 3) * STAGEB;
        uint32_t ab = st + aoff, bb = st + boff;
        #pragma unroll
        for (int kk = 0; kk < 2; kk++) {
            uint32_t af[4][4], bf[2][4];
            #pragma unroll
            for (int mt = 0; mt < 4; mt++)
                ldsm_x4(af[mt], ab + kk * 32 + mt * (16 * ROWB));
            ldsm_x4(bf[0], bb + kk * 32);
            ldsm_x4(bf[1], bb + kk * 32 + 16 * ROWB);
            #pragma unroll
            for (int mt = 0; mt < 4; mt++)
                #pragma unroll
                for (int nt = 0; nt < 4; nt++)
                    mma16816(acc[mt][nt], af[mt], &bf[nt >> 1][(nt & 1) * 2]);
        }
    }

    CP_WAIT(0);
    __syncthreads();
    int* tjs = (int*)sm;
    if (tid < 128) tjs[tid] = g_tgt[col0 + tid];
    __syncthreads();

    const float NEGINF = __int_as_float(0xff800000);
    #pragma unroll
    for (int mt = 0; mt < 4; mt++) {
        int r = row0 + warpM * 64 + mt * 16 + (lane >> 2);
        int ti0 = g_tgt[r], ti1 = g_tgt[r + 8];
        __half* C0 = C + (size_t)r * BN_;
        #pragma unroll
        for (int nt = 0; nt < 4; nt++) {
            int cl = warpN * 32 + nt * 8 + (lane & 3) * 2;
            int tj0 = tjs[cl], tj1 = tjs[cl + 1];
            float a0 = (ti0 == tj0) ? NEGINF : acc[mt][nt][0];
            float a1 = (ti0 == tj1) ? NEGINF : acc[mt][nt][1];
            float a2 = (ti1 == tj0) ? NEGINF : acc[mt][nt][2];
            float a3 = (ti1 == tj1) ? NEGINF : acc[mt][nt][3];
            *(__half2*)(C0 + col0 + cl) = __floats2half2_rn(a0, a1);
            *(__half2*)(C0 + 8 * BN_ + col0 + cl) = __floats2half2_rn(a2, a3);
        }
    }
    #undef ISSUE
}

// ================= per-row top-k via one-level value histogram ===============
__device__ __forceinline__ int val_bin(float v) {
    return min(1023, max(0, (int)((v + 1.0f) * 512.0f)));
}

__global__ void __launch_bounds__(256) rowloss_k() {
    __shared__ __half vals[BN_];            // 8 KB
    __shared__ unsigned hist[4][1024];      // 16 KB, 4 replicas
    __shared__ unsigned ws[8];
    __shared__ int s_b, s_c;
    __shared__ float s_m[2], s_S[2], redf[8];

    int row = blockIdx.x, tid = threadIdx.x;
    int lane = tid & 31, warp = tid >> 5;
    unsigned* myhist = hist[warp & 3];

    for (int mat = 0; mat < 2; mat++) {
        const uint4* R = (const uint4*)(g_S[mat] + (size_t)row * BN_);
        unsigned* hf = &hist[0][0];
        #pragma unroll
        for (int j = 0; j < 16; j++) hf[tid + j * 256] = 0;
        __syncthreads();

        float lmax = -1e30f;
        #pragma unroll
        for (int q = 0; q < 2; q++) {
            int j = tid + q * 256;              // uint4 idx, 8 halfs each
            uint4 u = R[j];
            ((uint4*)vals)[j] = u;
            #pragma unroll
            for (int p = 0; p < 4; p++) {
                unsigned uw = (&u.x)[p];
                float2 f = __half22float2(*(__half2*)&uw);
                lmax = fmaxf(lmax, fmaxf(f.x, f.y));
                atomicAdd(&myhist[val_bin(f.x)], 1u);
                atomicAdd(&myhist[val_bin(f.y)], 1u);
            }
        }
        #pragma unroll
        for (int o = 16; o; o >>= 1)
            lmax = fmaxf(lmax, __shfl_xor_sync(0xffffffffu, lmax, o));
        if (lane == 0) redf[warp] = lmax;
        __syncthreads();

        // ---- merge replicas + suffix scan over 1024 bins ----
        unsigned h0 = hist[0][4 * tid] + hist[1][4 * tid] + hist[2][4 * tid] + hist[3][4 * tid];
        unsigned h1 = hist[0][4 * tid + 1] + hist[1][4 * tid + 1] + hist[2][4 * tid + 1] + hist[3][4 * tid + 1];
        unsigned h2 = hist[0][4 * tid + 2] + hist[1][4 * tid + 2] + hist[2][4 * tid + 2] + hist[3][4 * tid + 2];
        unsigned h3 = hist[0][4 * tid + 3] + hist[1][4 * tid + 3] + hist[2][4 * tid + 3] + hist[3][4 * tid + 3];
        unsigned g = h0 + h1 + h2 + h3;
        unsigned v = g;
        #pragma unroll
        for (int off = 1; off < 32; off <<= 1) {
            unsigned u = __shfl_down_sync(0xffffffffu, v, off);
            if (lane + off < 32) v += u;
        }
        if (lane == 0) ws[warp] = v;
        __syncthreads();
        unsigned later = 0;
        #pragma unroll
        for (int w2 = 0; w2 < 8; w2++) if (w2 > warp) later += ws[w2];
        unsigned F_t = v + later;

        if (F_t >= (unsigned)KTOP && F_t - g < (unsigned)KTOP) {
            unsigned F = F_t - g;
            if (F + h3 >= (unsigned)KTOP) { s_b = 4 * tid + 3; s_c = (int)F; }
            else {
                F += h3;
                if (F + h2 >= (unsigned)KTOP) { s_b = 4 * tid + 2; s_c = (int)F; }
                else {
                    F += h2;
                    if (F + h1 >= (unsigned)KTOP) { s_b = 4 * tid + 1; s_c = (int)F; }
                    else { s_b = 4 * tid; s_c = (int)(F + h1); }
                }
            }
        }
        __syncthreads();

        int b1 = s_b;
        int r1 = KTOP - s_c;
        float m;
        {
            float t = redf[0];
            #pragma unroll
            for (int w2 = 1; w2 < 8; w2++) t = fmaxf(t, redf[w2]);
            m = t;
        }

        // ---- exp sweep over selected elements ----
        float local = 0.f;
        #pragma unroll
        for (int q = 0; q < 2; q++) {
            int j = tid + q * 256;
            uint4 u = ((const uint4*)vals)[j];
            #pragma unroll
            for (int p = 0; p < 4; p++) {
                unsigned uw = (&u.x)[p];
                float2 f = __half22float2(*(__half2*)&uw);
                if (val_bin(f.x) > b1) local += __expf(100.f * (f.x - m));
                if (val_bin(f.y) > b1) local += __expf(100.f * (f.y - m));
            }
        }
        #pragma unroll
        for (int o = 16; o; o >>= 1) local += __shfl_xor_sync(0xffffffffu, local, o);
        __syncthreads();
        if (lane == 0) redf[warp] = local;
        __syncthreads();
        if (tid == 0) {
            float t = 0.f;
            #pragma unroll
            for (int w2 = 0; w2 < 8; w2++) t += redf[w2];
            float mid = ((float)b1 + 0.5f) * (1.0f / 512.0f) - 1.0f;
            s_S[mat] = t + (float)r1 * __expf(100.f * (mid - m));
            s_m[mat] = m;
        }
        __syncthreads();
    }

    if (tid == 0) {
        float pos = g_pos[row];
        float M = fmaxf(fmaxf(s_m[0], s_m[1]), pos);
        float tot = __expf(100.f * (pos - M)) +
                    s_S[0] * __expf(100.f * (s_m[0] - M)) +
                    s_S[1] * __expf(100.f * (s_m[1] - M));
        g_rowloss[row] = 100.f * M + logf(tot) - 100.f * pos;
    }
}

// ---------------- final mean reduction ---------------------------------------
__global__ void finalize_k(float* __restrict__ out) {
    float s = 0.f;
    for (int j = threadIdx.x; j < BN_; j += 1024) s += g_rowloss[j];
    #pragma unroll
    for (int o = 16; o; o >>= 1) s += __shfl_xor_sync(0xffffffffu, s, o);
    __shared__ float red[32];
    int w = threadIdx.x >> 5, l = threadIdx.x & 31;
    if (l == 0) red[w] = s;
    __syncthreads();
    if (w == 0) {
        float t = red[l];
        #pragma unroll
        for (int o = 16; o; o >>= 1) t += __shfl_xor_sync(0xffffffffu, t, o);
        if (l == 0) out[0] = t * (1.0f / (float)BN_);
    }
}

// ---------------- launch ------------------------------------------------------
extern "C" void kernel_launch(void* const* d_in, const int* in_sizes, int n_in,
                              void* d_out, int out_size) {
    const float* feat     = (const float*)d_in[0];
    const float* feat_old = (const float*)d_in[1];
    const int*   tgt_raw  = (const int*)d_in[2];
    float* out = (float*)d_out;

    cudaFuncSetAttribute(gemm_mma_k, cudaFuncAttributeMaxDynamicSharedMemorySize,
                         GEMM_SMEM);

    extract_targets_k<<<1, 1024>>>(tgt_raw);
    prep_k<<<BN_, 128>>>(feat, feat_old);
    dim3 grid(BN_ / 128, BN_ / 128, 2);
    gemm_mma_k<<<grid, 256, GEMM_SMEM>>>();
    rowloss_k<<<BN_, 256>>>();
    finalize_k<<<1, 1024>>>(out);
}

// round 7
// speedup vs baseline: 7.4455x; 1.1096x over previous
#include <cuda_runtime.h>
#include <cuda_fp16.h>
#include <math.h>
#include <stdint.h>

#define BN_ 4096
#define DN_ 512
#define KTOP 1024
#define KEFF 512

// ---------------- scratch (device globals; allocation-free kernel_launch) ----
__device__ __half g_S[2][(size_t)BN_ * BN_]; // 0: fn@fo^T  1: fn@fn^T (67 MB)
__device__ __half g_Ah[(size_t)BN_ * KEFF]; // fnh (4 MB)
__device__ __half g_Bo[(size_t)BN_ * KEFF]; // foh (4 MB)
__device__ float g_pos[BN_];
__device__ float g_rowloss[BN_];
__device__ int   g_tgt[BN_];

// ================= small PTX helpers (sm_100-safe) ===========================
__device__ __forceinline__ uint32_t smem_u32(const void* p) {
    uint32_t a;
    asm("{ .reg .u64 t; cvta.to.shared.u64 t, %1; cvt.u32.u64 %0, t; }"
        : "=r"(a) : "l"(p));
    return a;
}
__device__ __forceinline__ void cp16(uint32_t dst, const void* src) {
    asm volatile("cp.async.cg.shared.global [%0], [%1], 16;" :: "r"(dst), "l"(src));
}
#define CP_COMMIT() asm volatile("cp.async.commit_group;" ::: "memory")
#define CP_WAIT(n)  asm volatile("cp.async.wait_group %0;" :: "n"(n) : "memory")

__device__ __forceinline__ void ldsm_x4(uint32_t* r, uint32_t addr) {
    asm volatile("ldmatrix.sync.aligned.m8n8.x4.shared.b16 {%0,%1,%2,%3}, [%4];"
                 : "=r"(r[0]), "=r"(r[1]), "=r"(r[2]), "=r"(r[3]) : "r"(addr));
}
__device__ __forceinline__ void mma16816(float* c, const uint32_t* a, const uint32_t* b) {
    asm volatile(
        "mma.sync.aligned.m16n8k16.row.col.f32.f16.f16.f32 "
        "{%0,%1,%2,%3}, {%4,%5,%6,%7}, {%8,%9}, {%0,%1,%2,%3};"
        : "+f"(c[0]), "+f"(c[1]), "+f"(c[2]), "+f"(c[3])
        : "r"(a[0]), "r"(a[1]), "r"(a[2]), "r"(a[3]), "r"(b[0]), "r"(b[1]));
}

// ---------------- targets: detect int64 vs int32, extract to int32 ----------
__global__ void extract_targets_k(const int* __restrict__ raw) {
    __shared__ int s_any;
    if (threadIdx.x == 0) s_any = 0;
    __syncthreads();
    int local = 0;
    for (int j = threadIdx.x; j < BN_; j += blockDim.x)
        if ((j & 1) && raw[j] != 0) local = 1;
    if (local) atomicOr(&s_any, 1);
    __syncthreads();
    int is64 = (s_any == 0);
    for (int j = threadIdx.x; j < BN_; j += blockDim.x)
        g_tgt[j] = is64 ? raw[2 * j] : raw[j];
}

// ---------------- fused prep: normalize both + fp16 cast + exact pos ---------
__global__ void prep_k(const float* __restrict__ feat,
                       const float* __restrict__ feat_old) {
    int row = blockIdx.x;
    const float* a = feat + (size_t)row * DN_;
    const float* b = feat_old + (size_t)row * DN_;

    float snn = 0.f, soo = 0.f, sno = 0.f;
    for (int j = threadIdx.x; j < DN_; j += 128) {
        float x = a[j], y = b[j];
        snn += x * x; soo += y * y; sno += x * y;
    }
    #pragma unroll
    for (int o = 16; o; o >>= 1) {
        snn += __shfl_xor_sync(0xffffffffu, snn, o);
        soo += __shfl_xor_sync(0xffffffffu, soo, o);
        sno += __shfl_xor_sync(0xffffffffu, sno, o);
    }
    __shared__ float red[3][4];
    int w = threadIdx.x >> 5, l = threadIdx.x & 31;
    if (l == 0) { red[0][w] = snn; red[1][w] = soo; red[2][w] = sno; }
    __syncthreads();
    float tn = red[0][0] + red[0][1] + red[0][2] + red[0][3];
    float to = red[1][0] + red[1][1] + red[1][2] + red[1][3];
    float tx = red[2][0] + red[2][1] + red[2][2] + red[2][3];
    float invn = 1.f / fmaxf(sqrtf(tn), 1e-12f);
    float invo = 1.f / fmaxf(sqrtf(to), 1e-12f);
    if (threadIdx.x == 0) g_pos[row] = tx * invn * invo;

    __half* An = g_Ah + (size_t)row * KEFF;
    __half* Bo = g_Bo + (size_t)row * KEFF;
    for (int j = threadIdx.x; j < DN_; j += 128) {
        An[j] = __float2half_rn(a[j] * invn);
        Bo[j] = __float2half_rn(b[j] * invo);
    }
}

// ================= mma.sync fp16 GEMM, symmetric mat1 ========================
#define KC 32
#define NITER (KEFF / KC)          // 16
#define ROWB 80
#define ATILE (128 * ROWB)
#define STAGEB (2 * ATILE)
#define TSTRIDE 132                // halfs; transpose stage stride
#define OFF_TJS 36864
#define GEMM_SMEM 81920

__global__ void __launch_bounds__(256, 2) gemm_mma_k() {
    int mat = blockIdx.z;
    int bx = blockIdx.x, by = blockIdx.y;
    if (mat == 1 && bx < by) return;          // symmetry: only upper triangle

    extern __shared__ char sm[];
    uint32_t sbase = smem_u32(sm);

    int tid = threadIdx.x, wid = tid >> 5, lane = tid & 31;
    int warpM = wid >> 2, warpN = wid & 3;
    const __half* Ag = g_Ah;
    const __half* Bg = mat ? g_Ah : g_Bo;
    __half* C = g_S[mat];
    int row0 = by * 128, col0 = bx * 128;

    int rA0 = tid >> 2, gA0 = tid & 3, rA1 = (tid + 256) >> 2;
    const char* pA0 = (const char*)(Ag + (size_t)(row0 + rA0) * KEFF) + gA0 * 16;
    const char* pA1 = (const char*)(Ag + (size_t)(row0 + rA1) * KEFF) + gA0 * 16;
    const char* pB0 = (const char*)(Bg + (size_t)(col0 + rA0) * KEFF) + gA0 * 16;
    const char* pB1 = (const char*)(Bg + (size_t)(col0 + rA1) * KEFF) + gA0 * 16;
    uint32_t dA0 = rA0 * ROWB + gA0 * 16, dA1 = rA1 * ROWB + gA0 * 16;
    uint32_t dB0 = ATILE + dA0, dB1 = ATILE + dA1;

    #define ISSUE(it) do {                                                     \
        uint32_t st = sbase + ((it) & 3) * STAGEB;                             \
        int ko = (it) * 64;                                                    \
        cp16(st + dA0, pA0 + ko); cp16(st + dA1, pA1 + ko);                    \
        cp16(st + dB0, pB0 + ko); cp16(st + dB1, pB1 + ko);                    \
    } while (0)

    ISSUE(0); CP_COMMIT();
    ISSUE(1); CP_COMMIT();
    ISSUE(2); CP_COMMIT();

    float acc[4][4][4] = {};
    uint32_t aoff = (uint32_t)((warpM * 64 + (lane & 15)) * ROWB + (lane >> 4) * 16);
    uint32_t boff = (uint32_t)(ATILE +
        (warpN * 32 + (lane & 7) + (lane >> 4) * 8) * ROWB + ((lane >> 3) & 1) * 16);

    for (int it = 0; it < NITER; it++) {
        CP_WAIT(2);
        __syncthreads();
        if (it + 3 < NITER) ISSUE(it + 3);
        CP_COMMIT();

        uint32_t st = sbase + (it & 3) * STAGEB;
        uint32_t ab = st + aoff, bb = st + boff;
        #pragma unroll
        for (int kk = 0; kk < 2; kk++) {
            uint32_t af[4][4], bf[2][4];
            #pragma unroll
            for (int mt = 0; mt < 4; mt++)
                ldsm_x4(af[mt], ab + kk * 32 + mt * (16 * ROWB));
            ldsm_x4(bf[0], bb + kk * 32);
            ldsm_x4(bf[1], bb + kk * 32 + 16 * ROWB);
            #pragma unroll
            for (int mt = 0; mt < 4; mt++)
                #pragma unroll
                for (int nt = 0; nt < 4; nt++)
                    mma16816(acc[mt][nt], af[mt], &bf[nt >> 1][(nt & 1) * 2]);
        }
    }

    CP_WAIT(0);
    __syncthreads();
    int* tjs = (int*)(sm + OFF_TJS);
    if (tid < 128) tjs[tid] = g_tgt[col0 + tid];
    __syncthreads();

    bool needT = (mat == 1) && (bx > by);
    __half* T = (__half*)sm;

    const float NEGINF = __int_as_float(0xff800000);
    #pragma unroll
    for (int mt = 0; mt < 4; mt++) {
        int rl = warpM * 64 + mt * 16 + (lane >> 2);
        int r = row0 + rl;
        int ti0 = g_tgt[r], ti1 = g_tgt[r + 8];
        __half* C0 = C + (size_t)r * BN_;
        #pragma unroll
        for (int nt = 0; nt < 4; nt++) {
            int cl = warpN * 32 + nt * 8 + (lane & 3) * 2;
            int tj0 = tjs[cl], tj1 = tjs[cl + 1];
            float a0 = (ti0 == tj0) ? NEGINF : acc[mt][nt][0];
            float a1 = (ti0 == tj1) ? NEGINF : acc[mt][nt][1];
            float a2 = (ti1 == tj0) ? NEGINF : acc[mt][nt][2];
            float a3 = (ti1 == tj1) ? NEGINF : acc[mt][nt][3];
            __half2 hv0 = __floats2half2_rn(a0, a1);
            __half2 hv1 = __floats2half2_rn(a2, a3);
            *(__half2*)(C0 + col0 + cl) = hv0;
            *(__half2*)(C0 + 8 * BN_ + col0 + cl) = hv1;
            if (needT) {
                *(__half2*)(T + rl * TSTRIDE + cl) = hv0;
                *(__half2*)(T + (rl + 8) * TSTRIDE + cl) = hv1;
            }
        }
    }

    if (needT) {
        __syncthreads();
        if (tid < 128) {
            __half* Crow = C + (size_t)(col0 + tid) * BN_ + row0;
            #pragma unroll
            for (int i = 0; i < 16; i++) {
                __half tmp[8];
                #pragma unroll
                for (int r2 = 0; r2 < 8; r2++)
                    tmp[r2] = T[(8 * i + r2) * TSTRIDE + tid];
                *(uint4*)(Crow + 8 * i) = *(uint4*)tmp;
            }
        }
    }
    #undef ISSUE
}

// ================= per-row top-k: integer half-key histogram =================
// key16(h) = monotone 16-bit key of half bits; bin = key >> 6 (1024 log bins).
// Selection only needs monotone bins; boundary residual valued at bin mid-key.
__device__ __forceinline__ unsigned key16(unsigned l) {
    unsigned s = l >> 15;
    return l ^ (0x8000u | (s * 0x7FFFu));
}
__device__ __forceinline__ float key2val(unsigned k) {
    unsigned b = (k & 0x8000u) ? (k ^ 0x8000u) : ((~k) & 0xFFFFu);
    __half h = __ushort_as_half((unsigned short)b);
    return __half2float(h);
}

__global__ void __launch_bounds__(256) rowloss_k() {
    __shared__ __half vals[BN_];            // 8 KB
    __shared__ unsigned hist[4][1024];      // 16 KB, 4 replicas
    __shared__ unsigned ws[8];
    __shared__ int s_b, s_c, s_bmax;
    __shared__ float s_m[2], s_S[2], redf[8];

    int row = blockIdx.x, tid = threadIdx.x;
    int lane = tid & 31, warp = tid >> 5;
    unsigned* myhist = hist[warp & 3];

    for (int mat = 0; mat < 2; mat++) {
        const uint4* R = (const uint4*)(g_S[mat] + (size_t)row * BN_);
        unsigned* hf = &hist[0][0];
        #pragma unroll
        for (int j = 0; j < 16; j++) hf[tid + j * 256] = 0;
        __syncthreads();

        #pragma unroll
        for (int q = 0; q < 2; q++) {
            int j = tid + q * 256;
            uint4 u = R[j];
            ((uint4*)vals)[j] = u;
            #pragma unroll
            for (int p = 0; p < 4; p++) {
                unsigned uw = (&u.x)[p];
                atomicAdd(&myhist[key16(uw & 0xFFFFu) >> 6], 1u);
                atomicAdd(&myhist[key16(uw >> 16) >> 6], 1u);
            }
        }
        __syncthreads();

        // ---- merge replicas + suffix scan; find K=KTOP and K=1 crossings ----
        unsigned h0 = hist[0][4 * tid] + hist[1][4 * tid] + hist[2][4 * tid] + hist[3][4 * tid];
        unsigned h1 = hist[0][4 * tid + 1] + hist[1][4 * tid + 1] + hist[2][4 * tid + 1] + hist[3][4 * tid + 1];
        unsigned h2 = hist[0][4 * tid + 2] + hist[1][4 * tid + 2] + hist[2][4 * tid + 2] + hist[3][4 * tid + 2];
        unsigned h3 = hist[0][4 * tid + 3] + hist[1][4 * tid + 3] + hist[2][4 * tid + 3] + hist[3][4 * tid + 3];
        unsigned g = h0 + h1 + h2 + h3;
        unsigned v = g;
        #pragma unroll
        for (int off = 1; off < 32; off <<= 1) {
            unsigned u = __shfl_down_sync(0xffffffffu, v, off);
            if (lane + off < 32) v += u;
        }
        if (lane == 0) ws[warp] = v;
        __syncthreads();
        unsigned later = 0;
        #pragma unroll
        for (int w2 = 0; w2 < 8; w2++) if (w2 > warp) later += ws[w2];
        unsigned F_t = v + later;

        if (F_t >= (unsigned)KTOP && F_t - g < (unsigned)KTOP) {
            unsigned F = F_t - g;
            if (F + h3 >= (unsigned)KTOP) { s_b = 4 * tid + 3; s_c = (int)F; }
            else {
                F += h3;
                if (F + h2 >= (unsigned)KTOP) { s_b = 4 * tid + 2; s_c = (int)F; }
                else {
                    F += h2;
                    if (F + h1 >= (unsigned)KTOP) { s_b = 4 * tid + 1; s_c = (int)F; }
                    else { s_b = 4 * tid; s_c = (int)(F + h1); }
                }
            }
        }
        if (F_t >= 1u && F_t - g < 1u) {   // topmost nonempty bin
            if (h3) s_bmax = 4 * tid + 3;
            else if (h2) s_bmax = 4 * tid + 2;
            else if (h1) s_bmax = 4 * tid + 1;
            else s_bmax = 4 * tid;
        }
        __syncthreads();

        int b1 = s_b;
        int r1 = KTOP - s_c;
        unsigned Tk = (unsigned)(b1 + 1) << 6;     // selected <=> key >= Tk
        float m = key2val((unsigned)(s_bmax + 1) << 6);  // upper edge of max bin

        // ---- exp sweep over selected elements ----
        float local = 0.f;
        #pragma unroll
        for (int q = 0; q < 2; q++) {
            int j = tid + q * 256;
            uint4 u = ((const uint4*)vals)[j];
            #pragma unroll
            for (int p = 0; p < 4; p++) {
                unsigned uw = (&u.x)[p];
                unsigned k0 = key16(uw & 0xFFFFu);
                unsigned k1 = key16(uw >> 16);
                if (k0 >= Tk) {
                    float f = __half2float(__ushort_as_half((unsigned short)(uw & 0xFFFFu)));
                    local += __expf(100.f * (f - m));
                }
                if (k1 >= Tk) {
                    float f = __half2float(__ushort_as_half((unsigned short)(uw >> 16)));
                    local += __expf(100.f * (f - m));
                }
            }
        }
        #pragma unroll
        for (int o = 16; o; o >>= 1) local += __shfl_xor_sync(0xffffffffu, local, o);
        if (lane == 0) redf[warp] = local;
        __syncthreads();
        if (tid == 0) {
            float t = 0.f;
            #pragma unroll
            for (int w2 = 0; w2 < 8; w2++) t += redf[w2];
            float mid = key2val(((unsigned)b1 << 6) + 32u);
            s_S[mat] = t + (float)r1 * __expf(100.f * (mid - m));
            s_m[mat] = m;
        }
        __syncthreads();
    }

    if (tid == 0) {
        float pos = g_pos[row];
        float M = fmaxf(fmaxf(s_m[0], s_m[1]), pos);
        float tot = __expf(100.f * (pos - M)) +
                    s_S[0] * __expf(100.f * (s_m[0] - M)) +
                    s_S[1] * __expf(100.f * (s_m[1] - M));
        g_rowloss[row] = 100.f * M + logf(tot) - 100.f * pos;
    }
}

// ---------------- final mean reduction ---------------------------------------
__global__ void finalize_k(float* __restrict__ out) {
    float s = 0.f;
    for (int j = threadIdx.x; j < BN_; j += 1024) s += g_rowloss[j];
    #pragma unroll
    for (int o = 16; o; o >>= 1) s += __shfl_xor_sync(0xffffffffu, s, o);
    __shared__ float red[32];
    int w = threadIdx.x >> 5, l = threadIdx.x & 31;
    if (l == 0) red[w] = s;
    __syncthreads();
    if (w == 0) {
        float t = red[l];
        #pragma unroll
        for (int o = 16; o; o >>= 1) t += __shfl_xor_sync(0xffffffffu, t, o);
        if (l == 0) out[0] = t * (1.0f / (float)BN_);
    }
}

// ---------------- launch ------------------------------------------------------
extern "C" void kernel_launch(void* const* d_in, const int* in_sizes, int n_in,
                              void* d_out, int out_size) {
    const float* feat     = (const float*)d_in[0];
    const float* feat_old = (const float*)d_in[1];
    const int*   tgt_raw  = (const int*)d_in[2];
    float* out = (float*)d_out;

    cudaFuncSetAttribute(gemm_mma_k, cudaFuncAttributeMaxDynamicSharedMemorySize,
                         GEMM_SMEM);

    extract_targets_k<<<1, 1024>>>(tgt_raw);
    prep_k<<<BN_, 128>>>(feat, feat_old);
    dim3 grid(32, 32, 2);
    gemm_mma_k<<<grid, 256, GEMM_SMEM>>>();
    rowloss_k<<<BN_, 256>>>();
    finalize_k<<<1, 1024>>>(out);
}